// round 12
// baseline (speedup 1.0000x reference)
#include <cuda_runtime.h>
#include <cuda_bf16.h>
#include <math.h>

#define N_NODES 100000
#define N_EDGES 1600000
#define IN_DIM  512
#define HID     64
#define OUTD    32

// ---------------- scratch (static device globals; no allocation) ----------------
__device__ int   g_deg[N_NODES];
__device__ float g_dinv[N_NODES];
__device__ int   g_off[N_NODES + 1];
__device__ int   g_cur[N_NODES];
__device__ int   g_srcs[N_EDGES];
__device__ float g_wgt[N_EDGES];
__device__ float g_h1[(size_t)N_NODES * HID];   // 25.6 MB
__device__ float g_h2[(size_t)N_NODES * OUTD];  // 12.8 MB
__device__ int   g_bsum[256];
__device__ int   g_is64;

// W1 pre-packed into per-lane mma fragments
__device__ uint4 g_w1p[8][1024];   // 128 KB

__device__ __forceinline__ int load_edge(const void* ei, int part, int e) {
    if (g_is64) return (int)((const long long*)ei)[(size_t)part * N_EDGES + e];
    return ((const int*)ei)[(size_t)part * N_EDGES + e];
}

__device__ __forceinline__ unsigned hi16(float f) {
    return __float_as_uint(f) >> 16;
}
__device__ __forceinline__ unsigned lo16(float f) {
    float hf = __uint_as_float(__float_as_uint(f) & 0xFFFF0000u);
    return __float_as_uint(f - hf) >> 16;
}

// ---------------- init: degree=1 + W1 fragment pre-pack + dtype detect ----------------
__global__ void k_init(const float* __restrict__ W1, const long long* __restrict__ ei) {
    int v = blockIdx.x * blockDim.x + threadIdx.x;
    if (v < N_NODES) g_deg[v] = 1;
    if (v < 8192) {
        int lane = v & 31, nt = (v >> 5) & 7, ks = (v >> 8) & 3, chunk = v >> 10;
        int q = lane & 3, lr = lane >> 2;
        int n = nt * 8 + lr;
        int k0 = chunk * 64 + ks * 16 + 2 * q;
        float w00 = W1[(size_t)k0 * 64 + n];
        float w01 = W1[(size_t)(k0 + 1) * 64 + n];
        float w10 = W1[(size_t)(k0 + 8) * 64 + n];
        float w11 = W1[(size_t)(k0 + 9) * 64 + n];
        uint4 f;
        f.x = hi16(w00) | (hi16(w01) << 16);
        f.y = hi16(w10) | (hi16(w11) << 16);
        f.z = lo16(w00) | (lo16(w01) << 16);
        f.w = lo16(w10) | (lo16(w11) << 16);
        g_w1p[chunk][(ks * 8 + nt) * 32 + lane] = f;
    }
    if (blockIdx.x == 0) {
        __shared__ int ok;
        if (threadIdx.x == 0) ok = 1;
        __syncthreads();
        for (int j = threadIdx.x; j < 2048; j += blockDim.x) {
            long long e = ei[j];
            if (e < 0 || e >= N_NODES) atomicExch(&ok, 0);
        }
        __syncthreads();
        if (threadIdx.x == 0) g_is64 = ok;
    }
}

__global__ void k_hist(const void* __restrict__ ei) {
    int e = blockIdx.x * blockDim.x + threadIdx.x;
    if (e < N_EDGES) atomicAdd(&g_deg[load_edge(ei, 1, e)], 1);
}

// ---------------- GEMM1: h1 = x @ W1; 256thr/CTA, one m16 tile per warp ----------------
#define BMG 128

__device__ __forceinline__ void mma16816(float* c, const unsigned* a, const unsigned* b) {
    asm volatile(
        "mma.sync.aligned.m16n8k16.row.col.f32.bf16.bf16.f32 "
        "{%0,%1,%2,%3}, {%4,%5,%6,%7}, {%8,%9}, {%0,%1,%2,%3};\n"
        : "+f"(c[0]), "+f"(c[1]), "+f"(c[2]), "+f"(c[3])
        : "r"(a[0]), "r"(a[1]), "r"(a[2]), "r"(a[3]), "r"(b[0]), "r"(b[1]));
}

__device__ __forceinline__ unsigned hi_pack(float2 v) {
    return __byte_perm(__float_as_uint(v.x), __float_as_uint(v.y), 0x7632);
}
__device__ __forceinline__ unsigned lo_pack(float2 v) {
    unsigned bx = __float_as_uint(v.x), by = __float_as_uint(v.y);
    float lx = v.x - __uint_as_float(bx & 0xFFFF0000u);
    float ly = v.y - __uint_as_float(by & 0xFFFF0000u);
    return __byte_perm(__float_as_uint(lx), __float_as_uint(ly), 0x7632);
}

__global__ __launch_bounds__(256, 3) void k_gemm1(const float* __restrict__ x) {
    __shared__ uint4 Bp[1024];

    const int t = threadIdx.x;
    const int warp = t >> 5, lane = t & 31;
    const int q = lane & 3, lr = lane >> 2;
    const int rbase = blockIdx.x * BMG + warp * 16;

    const int r0 = rbase + lr, r1 = rbase + lr + 8;
    const bool v0 = r0 < N_NODES, v1 = r1 < N_NODES;
    const float* xp0 = x + (size_t)(v0 ? r0 : 0) * IN_DIM;
    const float* xp1 = x + (size_t)(v1 ? r1 : 0) * IN_DIM;

    float acc[8][4];
#pragma unroll
    for (int n = 0; n < 8; n++)
#pragma unroll
        for (int j = 0; j < 4; j++) acc[n][j] = 0.f;

    float2 vc[4], vn[4];
    const int c0 = 2 * q;
    const float2 z2 = make_float2(0.f, 0.f);

    vc[0] = v0 ? __ldcs((const float2*)(xp0 + c0))     : z2;
    vc[1] = v0 ? __ldcs((const float2*)(xp0 + c0 + 8)) : z2;
    vc[2] = v1 ? __ldcs((const float2*)(xp1 + c0))     : z2;
    vc[3] = v1 ? __ldcs((const float2*)(xp1 + c0 + 8)) : z2;

    for (int kt = 0; kt < IN_DIM; kt += 64) {
        __syncthreads();
        {
            const uint4* src = g_w1p[kt >> 6];
#pragma unroll
            for (int i = 0; i < 4; i++) Bp[t + 256 * i] = src[t + 256 * i];
        }
        __syncthreads();

#pragma unroll
        for (int ks = 0; ks < 4; ks++) {
            int knext = kt + ks * 16 + 16;
            if (knext < IN_DIM) {
                vn[0] = v0 ? __ldcs((const float2*)(xp0 + knext + c0))     : z2;
                vn[1] = v0 ? __ldcs((const float2*)(xp0 + knext + c0 + 8)) : z2;
                vn[2] = v1 ? __ldcs((const float2*)(xp1 + knext + c0))     : z2;
                vn[3] = v1 ? __ldcs((const float2*)(xp1 + knext + c0 + 8)) : z2;
            }
            unsigned ah[4], al[4];
            ah[0] = hi_pack(vc[0]); ah[1] = hi_pack(vc[2]);
            ah[2] = hi_pack(vc[1]); ah[3] = hi_pack(vc[3]);
            al[0] = lo_pack(vc[0]); al[1] = lo_pack(vc[2]);
            al[2] = lo_pack(vc[1]); al[3] = lo_pack(vc[3]);

#pragma unroll
            for (int nt = 0; nt < 8; nt++) {
                uint4 f = Bp[(ks * 8 + nt) * 32 + lane];
                unsigned bh[2] = {f.x, f.y};
                unsigned bl[2] = {f.z, f.w};
                mma16816(acc[nt], ah, bh);
                mma16816(acc[nt], ah, bl);
                mma16816(acc[nt], al, bh);
            }
#pragma unroll
            for (int i = 0; i < 4; i++) vc[i] = vn[i];
        }
    }

#pragma unroll
    for (int nt = 0; nt < 8; nt++) {
        int col = nt * 8 + 2 * q;
        if (v0)
            *(float2*)&g_h1[(size_t)r0 * HID + col] = make_float2(acc[nt][0], acc[nt][1]);
        if (v1)
            *(float2*)&g_h1[(size_t)r1 * HID + col] = make_float2(acc[nt][2], acc[nt][3]);
    }
}

// ---------------- exclusive scan of (deg-1) to build CSR offsets ----------------
__global__ void k_scan1() {
    __shared__ int s[512];
    int t = threadIdx.x;
    int v = blockIdx.x * 512 + t;
    int c = (v < N_NODES) ? (g_deg[v] - 1) : 0;
    s[t] = c;
    __syncthreads();
    for (int o = 1; o < 512; o <<= 1) {
        int val = (t >= o) ? s[t - o] : 0;
        __syncthreads();
        s[t] += val;
        __syncthreads();
    }
    if (v < N_NODES) g_off[v] = s[t] - c;
    if (t == 511) g_bsum[blockIdx.x] = s[511];
}

__global__ void k_scan2(int nb) {
    __shared__ int s[256];
    int t = threadIdx.x;
    int c = (t < nb) ? g_bsum[t] : 0;
    s[t] = c;
    __syncthreads();
    for (int o = 1; o < 256; o <<= 1) {
        int val = (t >= o) ? s[t - o] : 0;
        __syncthreads();
        s[t] += val;
        __syncthreads();
    }
    if (t < nb) g_bsum[t] = s[t] - c;
}

__global__ void k_scan3() {
    int v = blockIdx.x * blockDim.x + threadIdx.x;
    if (v < N_NODES) {
        int o = g_off[v] + g_bsum[v >> 9];
        g_off[v] = o;
        g_cur[v] = o;
        g_dinv[v] = rsqrtf((float)g_deg[v]);
    }
    if (v == 0) g_off[N_NODES] = N_EDGES;
}

__global__ void k_scatter(const void* __restrict__ ei) {
    int e = blockIdx.x * blockDim.x + threadIdx.x;
    if (e < N_EDGES) {
        int d = load_edge(ei, 1, e);
        int s = load_edge(ei, 0, e);
        int pos = atomicAdd(&g_cur[d], 1);
        g_srcs[pos] = s;
        g_wgt[pos] = g_dinv[s] * g_dinv[d];
    }
}

#define FULLM 0xffffffffu

// ---------------- agg1: batched-index shuffle-broadcast gather + fused GEMV ----------------
__global__ __launch_bounds__(256) void k_agg1(const float* __restrict__ b1,
                                              const float* __restrict__ W2) {
    __shared__ float W2t[OUTD * 68];  // transposed W2, stride 68 (conflict-free LDS.128)
    __shared__ float ha[8][HID];
    int tid = threadIdx.x;
    for (int i = tid; i < HID * OUTD; i += 256) {
        int k = i >> 5, c = i & 31;
        W2t[c * 68 + k] = W2[k * OUTD + c];
    }
    __syncthreads();

    int w = tid >> 5, lane = tid & 31;
    int v = blockIdx.x * 8 + w;
    if (v >= N_NODES) return;

    int half = lane >> 4, hl = lane & 15;
    const float4* __restrict__ H = (const float4*)g_h1;  // 16 float4 per row
    float dv = g_dinv[v];
    float ax, ay, az, aw;
    {   // self loop (half 0 only contributes; same address both halves)
        float4 p = H[(size_t)v * 16 + hl];
        float wg = half ? 0.f : dv * dv;
        ax = wg * p.x; ay = wg * p.y; az = wg * p.z; aw = wg * p.w;
    }

    int e0 = g_off[v], end = g_off[v + 1];
    for (int base = e0; base < end; base += 32) {
        int idx = base + lane;
        bool vl = idx < end;
        int   sE = vl ? g_srcs[idx] : 0;   // one coalesced LDG per 32 edges
        float wE = vl ? g_wgt[idx] : 0.f;  // one coalesced LDG per 32 edges
        int n = min(32, end - base);
        int b = 0;
        for (; b + 8 <= n; b += 8) {  // 4 row-loads in flight per thread
            int   s0 = __shfl_sync(FULLM, sE, b + half);
            int   s1 = __shfl_sync(FULLM, sE, b + 2 + half);
            int   s2 = __shfl_sync(FULLM, sE, b + 4 + half);
            int   s3 = __shfl_sync(FULLM, sE, b + 6 + half);
            float w0 = __shfl_sync(FULLM, wE, b + half);
            float w1 = __shfl_sync(FULLM, wE, b + 2 + half);
            float w2 = __shfl_sync(FULLM, wE, b + 4 + half);
            float w3 = __shfl_sync(FULLM, wE, b + 6 + half);
            float4 p0 = H[(size_t)s0 * 16 + hl];
            float4 p1 = H[(size_t)s1 * 16 + hl];
            float4 p2 = H[(size_t)s2 * 16 + hl];
            float4 p3 = H[(size_t)s3 * 16 + hl];
            ax = fmaf(w0, p0.x, ax); ay = fmaf(w0, p0.y, ay);
            az = fmaf(w0, p0.z, az); aw = fmaf(w0, p0.w, aw);
            ax = fmaf(w1, p1.x, ax); ay = fmaf(w1, p1.y, ay);
            az = fmaf(w1, p1.z, az); aw = fmaf(w1, p1.w, aw);
            ax = fmaf(w2, p2.x, ax); ay = fmaf(w2, p2.y, ay);
            az = fmaf(w2, p2.z, az); aw = fmaf(w2, p2.w, aw);
            ax = fmaf(w3, p3.x, ax); ay = fmaf(w3, p3.y, ay);
            az = fmaf(w3, p3.z, az); aw = fmaf(w3, p3.w, aw);
        }
        for (; b + 2 <= n; b += 2) {
            int   s0 = __shfl_sync(FULLM, sE, b + half);
            float w0 = __shfl_sync(FULLM, wE, b + half);
            float4 p0 = H[(size_t)s0 * 16 + hl];
            ax = fmaf(w0, p0.x, ax); ay = fmaf(w0, p0.y, ay);
            az = fmaf(w0, p0.z, az); aw = fmaf(w0, p0.w, aw);
        }
        if (b < n) {  // odd tail: half 0 accumulates only
            int   s0 = __shfl_sync(FULLM, sE, b);
            float w0 = __shfl_sync(FULLM, wE, b);
            float wr = half ? 0.f : w0;
            float4 p0 = H[(size_t)s0 * 16 + hl];
            ax = fmaf(wr, p0.x, ax); ay = fmaf(wr, p0.y, ay);
            az = fmaf(wr, p0.z, az); aw = fmaf(wr, p0.w, aw);
        }
    }
    ax += __shfl_xor_sync(FULLM, ax, 16);
    ay += __shfl_xor_sync(FULLM, ay, 16);
    az += __shfl_xor_sync(FULLM, az, 16);
    aw += __shfl_xor_sync(FULLM, aw, 16);

    if (!half) {
        float4 bb = *(const float4*)(b1 + hl * 4);
        float4 r;
        r.x = fmaxf(ax + bb.x, 0.f);
        r.y = fmaxf(ay + bb.y, 0.f);
        r.z = fmaxf(az + bb.z, 0.f);
        r.w = fmaxf(aw + bb.w, 0.f);
        *(float4*)&ha[w][hl * 4] = r;
    }
    __syncwarp();

    // layer-2 GEMV: both operands via LDS.128
    float acc = 0.f;
    const float4* W4 = (const float4*)&W2t[lane * 68];
    const float4* hv = (const float4*)ha[w];
#pragma unroll
    for (int k4 = 0; k4 < 16; k4++) {
        float4 hh = hv[k4];
        float4 ww = W4[k4];
        acc = fmaf(hh.x, ww.x, acc);
        acc = fmaf(hh.y, ww.y, acc);
        acc = fmaf(hh.z, ww.z, acc);
        acc = fmaf(hh.w, ww.w, acc);
    }
    g_h2[(size_t)v * OUTD + lane] = acc;
}

// ---------------- agg2: quarter-warp quads + shuffle-broadcast + log_softmax ----------------
__global__ __launch_bounds__(256) void k_agg2(const float* __restrict__ b2,
                                              float* __restrict__ out) {
    int tid = threadIdx.x;
    int w = tid >> 5, lane = tid & 31;
    int v = blockIdx.x * 8 + w;
    if (v >= N_NODES) return;

    int sub = lane >> 3, j = lane & 7;  // 4 subs x 8 lanes; row = 8 float4 = 32 floats
    const float4* __restrict__ H = (const float4*)g_h2;
    float dv = g_dinv[v];
    float a0, a1, a2, a3;
    {
        float4 p = H[(size_t)v * 8 + j];
        float wg = sub ? 0.f : dv * dv;
        a0 = wg * p.x; a1 = wg * p.y; a2 = wg * p.z; a3 = wg * p.w;
    }

    int e0 = g_off[v], end = g_off[v + 1];
    for (int base = e0; base < end; base += 32) {
        int idx = base + lane;
        bool vl = idx < end;
        int   sE = vl ? g_srcs[idx] : 0;
        float wE = vl ? g_wgt[idx] : 0.f;
        int n = min(32, end - base);
        int b = 0;
        for (; b + 8 <= n; b += 8) {  // 2 quads in flight
            int   s0 = __shfl_sync(FULLM, sE, b + sub);
            int   s1 = __shfl_sync(FULLM, sE, b + 4 + sub);
            float w0 = __shfl_sync(FULLM, wE, b + sub);
            float w1 = __shfl_sync(FULLM, wE, b + 4 + sub);
            float4 p0 = H[(size_t)s0 * 8 + j];
            float4 p1 = H[(size_t)s1 * 8 + j];
            a0 = fmaf(w0, p0.x, a0); a1 = fmaf(w0, p0.y, a1);
            a2 = fmaf(w0, p0.z, a2); a3 = fmaf(w0, p0.w, a3);
            a0 = fmaf(w1, p1.x, a0); a1 = fmaf(w1, p1.y, a1);
            a2 = fmaf(w1, p1.z, a2); a3 = fmaf(w1, p1.w, a3);
        }
        for (; b + 4 <= n; b += 4) {
            int   s0 = __shfl_sync(FULLM, sE, b + sub);
            float w0 = __shfl_sync(FULLM, wE, b + sub);
            float4 p0 = H[(size_t)s0 * 8 + j];
            a0 = fmaf(w0, p0.x, a0); a1 = fmaf(w0, p0.y, a1);
            a2 = fmaf(w0, p0.z, a2); a3 = fmaf(w0, p0.w, a3);
        }
        if (b < n) {  // 1..3 left: mask invalid subs
            int m = b + sub;
            bool val = m < n;
            int lsel = val ? m : b;
            int   s0 = __shfl_sync(FULLM, sE, lsel);
            float w0 = __shfl_sync(FULLM, wE, lsel);
            if (!val) w0 = 0.f;
            float4 p0 = H[(size_t)s0 * 8 + j];
            a0 = fmaf(w0, p0.x, a0); a1 = fmaf(w0, p0.y, a1);
            a2 = fmaf(w0, p0.z, a2); a3 = fmaf(w0, p0.w, a3);
        }
    }
    // reduce across the 4 subs
    a0 += __shfl_xor_sync(FULLM, a0, 8);  a0 += __shfl_xor_sync(FULLM, a0, 16);
    a1 += __shfl_xor_sync(FULLM, a1, 8);  a1 += __shfl_xor_sync(FULLM, a1, 16);
    a2 += __shfl_xor_sync(FULLM, a2, 8);  a2 += __shfl_xor_sync(FULLM, a2, 16);
    a3 += __shfl_xor_sync(FULLM, a3, 8);  a3 += __shfl_xor_sync(FULLM, a3, 16);

    float4 bb = *(const float4*)(b2 + 4 * j);
    a0 += bb.x; a1 += bb.y; a2 += bb.z; a3 += bb.w;

    // log_softmax over 32 cols spread across j=0..7 (x4 each)
    float m = fmaxf(fmaxf(a0, a1), fmaxf(a2, a3));
    m = fmaxf(m, __shfl_xor_sync(FULLM, m, 1));
    m = fmaxf(m, __shfl_xor_sync(FULLM, m, 2));
    m = fmaxf(m, __shfl_xor_sync(FULLM, m, 4));
    float s = expf(a0 - m) + expf(a1 - m) + expf(a2 - m) + expf(a3 - m);
    s += __shfl_xor_sync(FULLM, s, 1);
    s += __shfl_xor_sync(FULLM, s, 2);
    s += __shfl_xor_sync(FULLM, s, 4);
    float ls = m + logf(s);

    if (sub == 0)
        *(float4*)&out[(size_t)v * OUTD + 4 * j] =
            make_float4(a0 - ls, a1 - ls, a2 - ls, a3 - ls);
}

// ---------------- launch: fork gemm1 onto a side stream to overlap preproc ----------------
extern "C" void kernel_launch(void* const* d_in, const int* in_sizes, int n_in,
                              void* d_out, int out_size) {
    const float* x  = (const float*)d_in[0];
    const void*  ei = d_in[1];
    const float* W1 = (const float*)d_in[2];
    const float* b1 = (const float*)d_in[3];
    const float* W2 = (const float*)d_in[4];
    const float* b2 = (const float*)d_in[5];
    float* out = (float*)d_out;

    static cudaStream_t s2;
    static cudaEvent_t evA, evB;
    static bool ready = false;
    if (!ready) {  // handle caching only; identical work every call
        cudaStreamCreateWithFlags(&s2, cudaStreamNonBlocking);
        cudaEventCreateWithFlags(&evA, cudaEventDisableTiming);
        cudaEventCreateWithFlags(&evB, cudaEventDisableTiming);
        ready = true;
    }

    k_init<<<(N_NODES + 255) / 256, 256>>>(W1, (const long long*)ei);
    cudaEventRecord(evA, 0);
    cudaStreamWaitEvent(s2, evA, 0);

    k_hist<<<(N_EDGES + 255) / 256, 256>>>(ei);
    int nb = (N_NODES + 511) / 512;
    k_scan1<<<nb, 512>>>();

    // (4) gemm1 on side stream — overlaps the edge pipeline
    k_gemm1<<<(N_NODES + BMG - 1) / BMG, 256, 0, s2>>>(x);
    cudaEventRecord(evB, s2);

    k_scan2<<<1, 256>>>(nb);
    k_scan3<<<(N_NODES + 255) / 256, 256>>>();
    k_scatter<<<(N_EDGES + 255) / 256, 256>>>(ei);

    cudaStreamWaitEvent(0, evB, 0);
    k_agg1<<<(N_NODES + 7) / 8, 256>>>(b1, W2);
    k_agg2<<<(N_NODES + 7) / 8, 256>>>(b2, out);
}

// round 13
// speedup vs baseline: 1.0190x; 1.0190x over previous
#include <cuda_runtime.h>
#include <cuda_bf16.h>
#include <math.h>

#define N_NODES 100000
#define N_EDGES 1600000
#define IN_DIM  512
#define HID     64
#define OUTD    32

// ---------------- scratch (static device globals; no allocation) ----------------
__device__ int   g_deg[N_NODES];
__device__ float g_dinv[N_NODES];
__device__ int   g_off[N_NODES + 1];
__device__ int   g_cur[N_NODES];
__device__ int2  g_ew[N_EDGES];     // {src, bitcast(wgt)} fused edge record
__device__ float g_h1[(size_t)N_NODES * HID];   // 25.6 MB
__device__ float g_h2[(size_t)N_NODES * OUTD];  // 12.8 MB (pre-scaled by dinv[v])
__device__ int   g_bsum[256];
__device__ int   g_is64;

// W1 pre-packed into per-lane mma fragments
__device__ uint4 g_w1p[8][1024];   // 128 KB

__device__ __forceinline__ int load_edge(const void* ei, int part, int e) {
    if (g_is64) return (int)((const long long*)ei)[(size_t)part * N_EDGES + e];
    return ((const int*)ei)[(size_t)part * N_EDGES + e];
}

__device__ __forceinline__ unsigned hi16(float f) {
    return __float_as_uint(f) >> 16;
}
__device__ __forceinline__ unsigned lo16(float f) {
    float hf = __uint_as_float(__float_as_uint(f) & 0xFFFF0000u);
    return __float_as_uint(f - hf) >> 16;
}

// ---------------- init: degree=1 + W1 fragment pre-pack + dtype detect ----------------
__global__ void k_init(const float* __restrict__ W1, const long long* __restrict__ ei) {
    int v = blockIdx.x * blockDim.x + threadIdx.x;
    if (v < N_NODES) g_deg[v] = 1;
    if (v < 8192) {
        int lane = v & 31, nt = (v >> 5) & 7, ks = (v >> 8) & 3, chunk = v >> 10;
        int q = lane & 3, lr = lane >> 2;
        int n = nt * 8 + lr;
        int k0 = chunk * 64 + ks * 16 + 2 * q;
        float w00 = W1[(size_t)k0 * 64 + n];
        float w01 = W1[(size_t)(k0 + 1) * 64 + n];
        float w10 = W1[(size_t)(k0 + 8) * 64 + n];
        float w11 = W1[(size_t)(k0 + 9) * 64 + n];
        uint4 f;
        f.x = hi16(w00) | (hi16(w01) << 16);
        f.y = hi16(w10) | (hi16(w11) << 16);
        f.z = lo16(w00) | (lo16(w01) << 16);
        f.w = lo16(w10) | (lo16(w11) << 16);
        g_w1p[chunk][(ks * 8 + nt) * 32 + lane] = f;
    }
    if (blockIdx.x == 0) {
        __shared__ int ok;
        if (threadIdx.x == 0) ok = 1;
        __syncthreads();
        for (int j = threadIdx.x; j < 2048; j += blockDim.x) {
            long long e = ei[j];
            if (e < 0 || e >= N_NODES) atomicExch(&ok, 0);
        }
        __syncthreads();
        if (threadIdx.x == 0) g_is64 = ok;
    }
}

__global__ void k_hist(const void* __restrict__ ei) {
    int e = blockIdx.x * blockDim.x + threadIdx.x;
    if (e < N_EDGES) atomicAdd(&g_deg[load_edge(ei, 1, e)], 1);
}

// ---------------- GEMM1: h1 = x @ W1; 256thr/CTA, one m16 tile per warp ----------------
#define BMG 128

__device__ __forceinline__ void mma16816(float* c, const unsigned* a, const unsigned* b) {
    asm volatile(
        "mma.sync.aligned.m16n8k16.row.col.f32.bf16.bf16.f32 "
        "{%0,%1,%2,%3}, {%4,%5,%6,%7}, {%8,%9}, {%0,%1,%2,%3};\n"
        : "+f"(c[0]), "+f"(c[1]), "+f"(c[2]), "+f"(c[3])
        : "r"(a[0]), "r"(a[1]), "r"(a[2]), "r"(a[3]), "r"(b[0]), "r"(b[1]));
}

__device__ __forceinline__ unsigned hi_pack(float2 v) {
    return __byte_perm(__float_as_uint(v.x), __float_as_uint(v.y), 0x7632);
}
__device__ __forceinline__ unsigned lo_pack(float2 v) {
    unsigned bx = __float_as_uint(v.x), by = __float_as_uint(v.y);
    float lx = v.x - __uint_as_float(bx & 0xFFFF0000u);
    float ly = v.y - __uint_as_float(by & 0xFFFF0000u);
    return __byte_perm(__float_as_uint(lx), __float_as_uint(ly), 0x7632);
}

__global__ __launch_bounds__(256, 3) void k_gemm1(const float* __restrict__ x) {
    __shared__ uint4 Bp[1024];

    const int t = threadIdx.x;
    const int warp = t >> 5, lane = t & 31;
    const int q = lane & 3, lr = lane >> 2;
    const int rbase = blockIdx.x * BMG + warp * 16;

    const int r0 = rbase + lr, r1 = rbase + lr + 8;
    const bool v0 = r0 < N_NODES, v1 = r1 < N_NODES;
    const float* xp0 = x + (size_t)(v0 ? r0 : 0) * IN_DIM;
    const float* xp1 = x + (size_t)(v1 ? r1 : 0) * IN_DIM;

    float acc[8][4];
#pragma unroll
    for (int n = 0; n < 8; n++)
#pragma unroll
        for (int j = 0; j < 4; j++) acc[n][j] = 0.f;

    float2 vc[4], vn[4];
    const int c0 = 2 * q;
    const float2 z2 = make_float2(0.f, 0.f);

    vc[0] = v0 ? __ldcs((const float2*)(xp0 + c0))     : z2;
    vc[1] = v0 ? __ldcs((const float2*)(xp0 + c0 + 8)) : z2;
    vc[2] = v1 ? __ldcs((const float2*)(xp1 + c0))     : z2;
    vc[3] = v1 ? __ldcs((const float2*)(xp1 + c0 + 8)) : z2;

    for (int kt = 0; kt < IN_DIM; kt += 64) {
        __syncthreads();
        {
            const uint4* src = g_w1p[kt >> 6];
#pragma unroll
            for (int i = 0; i < 4; i++) Bp[t + 256 * i] = src[t + 256 * i];
        }
        __syncthreads();

#pragma unroll
        for (int ks = 0; ks < 4; ks++) {
            int knext = kt + ks * 16 + 16;
            if (knext < IN_DIM) {
                vn[0] = v0 ? __ldcs((const float2*)(xp0 + knext + c0))     : z2;
                vn[1] = v0 ? __ldcs((const float2*)(xp0 + knext + c0 + 8)) : z2;
                vn[2] = v1 ? __ldcs((const float2*)(xp1 + knext + c0))     : z2;
                vn[3] = v1 ? __ldcs((const float2*)(xp1 + knext + c0 + 8)) : z2;
            }
            unsigned ah[4], al[4];
            ah[0] = hi_pack(vc[0]); ah[1] = hi_pack(vc[2]);
            ah[2] = hi_pack(vc[1]); ah[3] = hi_pack(vc[3]);
            al[0] = lo_pack(vc[0]); al[1] = lo_pack(vc[2]);
            al[2] = lo_pack(vc[1]); al[3] = lo_pack(vc[3]);

#pragma unroll
            for (int nt = 0; nt < 8; nt++) {
                uint4 f = Bp[(ks * 8 + nt) * 32 + lane];
                unsigned bh[2] = {f.x, f.y};
                unsigned bl[2] = {f.z, f.w};
                mma16816(acc[nt], ah, bh);
                mma16816(acc[nt], ah, bl);
                mma16816(acc[nt], al, bh);
            }
#pragma unroll
            for (int i = 0; i < 4; i++) vc[i] = vn[i];
        }
    }

#pragma unroll
    for (int nt = 0; nt < 8; nt++) {
        int col = nt * 8 + 2 * q;
        if (v0)
            *(float2*)&g_h1[(size_t)r0 * HID + col] = make_float2(acc[nt][0], acc[nt][1]);
        if (v1)
            *(float2*)&g_h1[(size_t)r1 * HID + col] = make_float2(acc[nt][2], acc[nt][3]);
    }
}

// ---------------- exclusive scan of (deg-1) to build CSR offsets ----------------
__global__ void k_scan1() {
    __shared__ int s[512];
    int t = threadIdx.x;
    int v = blockIdx.x * 512 + t;
    int c = (v < N_NODES) ? (g_deg[v] - 1) : 0;
    s[t] = c;
    __syncthreads();
    for (int o = 1; o < 512; o <<= 1) {
        int val = (t >= o) ? s[t - o] : 0;
        __syncthreads();
        s[t] += val;
        __syncthreads();
    }
    if (v < N_NODES) g_off[v] = s[t] - c;
    if (t == 511) g_bsum[blockIdx.x] = s[511];
}

__global__ void k_scan2(int nb) {
    __shared__ int s[256];
    int t = threadIdx.x;
    int c = (t < nb) ? g_bsum[t] : 0;
    s[t] = c;
    __syncthreads();
    for (int o = 1; o < 256; o <<= 1) {
        int val = (t >= o) ? s[t - o] : 0;
        __syncthreads();
        s[t] += val;
        __syncthreads();
    }
    if (t < nb) g_bsum[t] = s[t] - c;
}

__global__ void k_scan3() {
    int v = blockIdx.x * blockDim.x + threadIdx.x;
    if (v < N_NODES) {
        int o = g_off[v] + g_bsum[v >> 9];
        g_off[v] = o;
        g_cur[v] = o;
        g_dinv[v] = rsqrtf((float)g_deg[v]);
    }
    if (v == 0) g_off[N_NODES] = N_EDGES;
}

__global__ void k_scatter(const void* __restrict__ ei) {
    int e = blockIdx.x * blockDim.x + threadIdx.x;
    if (e < N_EDGES) {
        int d = load_edge(ei, 1, e);
        int s = load_edge(ei, 0, e);
        int pos = atomicAdd(&g_cur[d], 1);
        int2 ew;
        ew.x = s;
        ew.y = __float_as_int(g_dinv[s] * g_dinv[d]);
        g_ew[pos] = ew;  // one STG.64
    }
}

// ---------------- agg1: half-warp float4 gather (fused int2 edges) + fused GEMV ----------------
__global__ __launch_bounds__(256) void k_agg1(const float* __restrict__ b1,
                                              const float* __restrict__ W2) {
    __shared__ float W2s[HID * OUTD];
    __shared__ float ha[8][HID];
    int tid = threadIdx.x;
    for (int i = tid; i < HID * OUTD; i += 256) W2s[i] = W2[i];
    __syncthreads();

    int w = tid >> 5, lane = tid & 31;
    int v = blockIdx.x * 8 + w;
    if (v >= N_NODES) return;

    int half = lane >> 4, hl = lane & 15;
    const float4* __restrict__ H = (const float4*)g_h1;  // 16 float4 per row
    float dv = g_dinv[v];
    float ax = 0.f, ay = 0.f, az = 0.f, aw = 0.f;

    if (!half) {  // self loop once
        float4 p = H[(size_t)v * 16 + hl];
        float wg = dv * dv;
        ax = wg * p.x; ay = wg * p.y; az = wg * p.z; aw = wg * p.w;
    }
    int e = g_off[v] + half, end = g_off[v + 1];
    for (; e + 4 < end; e += 6) {  // 3 edges per parity stream in flight
        int2 ew0 = g_ew[e], ew1 = g_ew[e + 2], ew2 = g_ew[e + 4];  // 3 LDG.64
        float w0 = __int_as_float(ew0.y);
        float w1 = __int_as_float(ew1.y);
        float w2 = __int_as_float(ew2.y);
        float4 p0 = H[(size_t)ew0.x * 16 + hl];
        float4 p1 = H[(size_t)ew1.x * 16 + hl];
        float4 p2 = H[(size_t)ew2.x * 16 + hl];
        ax = fmaf(w0, p0.x, ax); ay = fmaf(w0, p0.y, ay);
        az = fmaf(w0, p0.z, az); aw = fmaf(w0, p0.w, aw);
        ax = fmaf(w1, p1.x, ax); ay = fmaf(w1, p1.y, ay);
        az = fmaf(w1, p1.z, az); aw = fmaf(w1, p1.w, aw);
        ax = fmaf(w2, p2.x, ax); ay = fmaf(w2, p2.y, ay);
        az = fmaf(w2, p2.z, az); aw = fmaf(w2, p2.w, aw);
    }
    for (; e < end; e += 2) {
        int2 ew0 = g_ew[e];
        float wg = __int_as_float(ew0.y);
        float4 p = H[(size_t)ew0.x * 16 + hl];
        ax = fmaf(wg, p.x, ax); ay = fmaf(wg, p.y, ay);
        az = fmaf(wg, p.z, az); aw = fmaf(wg, p.w, aw);
    }
    ax += __shfl_xor_sync(0xffffffffu, ax, 16);
    ay += __shfl_xor_sync(0xffffffffu, ay, 16);
    az += __shfl_xor_sync(0xffffffffu, az, 16);
    aw += __shfl_xor_sync(0xffffffffu, aw, 16);

    if (!half) {
        float4 bb = *(const float4*)(b1 + hl * 4);
        float4 r;
        r.x = fmaxf(ax + bb.x, 0.f);
        r.y = fmaxf(ay + bb.y, 0.f);
        r.z = fmaxf(az + bb.z, 0.f);
        r.w = fmaxf(aw + bb.w, 0.f);
        *(float4*)&ha[w][hl * 4] = r;
    }
    __syncwarp();

    // layer-2 GEMV; store h2' = dinv[v] * (ha . W2)   (pre-scaled for agg2)
    float acc = 0.f;
#pragma unroll
    for (int k = 0; k < HID; k++) acc = fmaf(ha[w][k], W2s[k * OUTD + lane], acc);
    g_h2[(size_t)v * OUTD + lane] = dv * acc;
}

// ---------------- agg2: unweighted sum of pre-scaled h2' + log_softmax ----------------
// out[v] = dinv[v] * (sum_{u in N(v)} h2'[u] + h2'[v]) + b2
__global__ __launch_bounds__(256) void k_agg2(const float* __restrict__ b2,
                                              float* __restrict__ out) {
    int tid = threadIdx.x;
    int w = tid >> 5, lane = tid & 31;
    int v = blockIdx.x * 8 + w;
    if (v >= N_NODES) return;

    int half = lane >> 4, hl = lane & 15;
    const float2* __restrict__ H = (const float2*)g_h2;  // 16 float2 per row
    float dv = g_dinv[v];
    float ax = 0.f, ay = 0.f;

    if (!half) {  // self loop: + h2'[v]
        float2 p = H[(size_t)v * 16 + hl];
        ax = p.x; ay = p.y;
    }
    int e = g_off[v] + half, end = g_off[v + 1];
    for (; e + 4 < end; e += 6) {
        int s0 = g_ew[e].x, s1 = g_ew[e + 2].x, s2 = g_ew[e + 4].x;
        float2 p0 = H[(size_t)s0 * 16 + hl];
        float2 p1 = H[(size_t)s1 * 16 + hl];
        float2 p2 = H[(size_t)s2 * 16 + hl];
        ax += p0.x; ay += p0.y;
        ax += p1.x; ay += p1.y;
        ax += p2.x; ay += p2.y;
    }
    for (; e < end; e += 2) {
        int s = g_ew[e].x;
        float2 p = H[(size_t)s * 16 + hl];
        ax += p.x; ay += p.y;
    }
    ax += __shfl_xor_sync(0xffffffffu, ax, 16);
    ay += __shfl_xor_sync(0xffffffffu, ay, 16);

    ax = fmaf(dv, ax, b2[2 * hl]);
    ay = fmaf(dv, ay, b2[2 * hl + 1]);

    float m = fmaxf(ax, ay);
#pragma unroll
    for (int o = 1; o < 16; o <<= 1) m = fmaxf(m, __shfl_xor_sync(0xffffffffu, m, o));
    float ex = expf(ax - m) + expf(ay - m);
#pragma unroll
    for (int o = 1; o < 16; o <<= 1) ex += __shfl_xor_sync(0xffffffffu, ex, o);
    float ls = logf(ex);
    if (!half)
        *(float2*)&out[(size_t)v * OUTD + 2 * hl] = make_float2(ax - m - ls, ay - m - ls);
}

// ---------------- launch: fork gemm1 onto a side stream to overlap preproc ----------------
extern "C" void kernel_launch(void* const* d_in, const int* in_sizes, int n_in,
                              void* d_out, int out_size) {
    const float* x  = (const float*)d_in[0];
    const void*  ei = d_in[1];
    const float* W1 = (const float*)d_in[2];
    const float* b1 = (const float*)d_in[3];
    const float* W2 = (const float*)d_in[4];
    const float* b2 = (const float*)d_in[5];
    float* out = (float*)d_out;

    static cudaStream_t s2;
    static cudaEvent_t evA, evB;
    static bool ready = false;
    if (!ready) {  // handle caching only; identical work every call
        cudaStreamCreateWithFlags(&s2, cudaStreamNonBlocking);
        cudaEventCreateWithFlags(&evA, cudaEventDisableTiming);
        cudaEventCreateWithFlags(&evB, cudaEventDisableTiming);
        ready = true;
    }

    k_init<<<(N_NODES + 255) / 256, 256>>>(W1, (const long long*)ei);
    cudaEventRecord(evA, 0);
    cudaStreamWaitEvent(s2, evA, 0);

    k_hist<<<(N_EDGES + 255) / 256, 256>>>(ei);
    int nb = (N_NODES + 511) / 512;
    k_scan1<<<nb, 512>>>();

    // (4) gemm1 on side stream — overlaps the edge pipeline
    k_gemm1<<<(N_NODES + BMG - 1) / BMG, 256, 0, s2>>>(x);
    cudaEventRecord(evB, s2);

    k_scan2<<<1, 256>>>(nb);
    k_scan3<<<(N_NODES + 255) / 256, 256>>>();
    k_scatter<<<(N_EDGES + 255) / 256, 256>>>(ei);

    cudaStreamWaitEvent(0, evB, 0);
    k_agg1<<<(N_NODES + 7) / 8, 256>>>(b1, W2);
    k_agg2<<<(N_NODES + 7) / 8, 256>>>(b2, out);
}